// round 15
// baseline (speedup 1.0000x reference)
#include <cuda_runtime.h>
#include <cuda_bf16.h>
#include <math.h>
#include <stdint.h>

// ---------------- problem constants ----------------
#define DD   512
#define SS   3
#define BB   256
#define HH   8
#define HD_  64
#define CHAIN_M 10          // chain steps m=1..10 -> Taylor terms k=2..21

// ---------------- scratch (device globals; no allocation) ----------------
__device__ float g_h1pre [BB*DD];
__device__ float g_delta [BB];
__device__ float g_dbx   [BB*DD];
__device__ float g_rs    [CHAIN_M*2*BB];
__device__ float g_hssm  [BB*DD];
__device__ float g_gates [SS*BB*4*DD];
__device__ float g_q     [BB*DD];
__device__ float g_kv    [SS*BB*2*DD];
__device__ float g_fused [BB*DD];
__device__ float g_outpre[BB*DD];

// bf16 hi/lo split buffers
__device__ __nv_bfloat16 g_xhi  [BB*DD],          g_xlo  [BB*DD];
__device__ __nv_bfloat16 g_lhhi [SS*BB*DD],       g_lhlo [SS*BB*DD];
__device__ __nv_bfloat16 g_wihhi[SS*4*DD*DD],     g_wihlo[SS*4*DD*DD];
__device__ __nv_bfloat16 g_whhhi[SS*4*DD*DD],     g_whhlo[SS*4*DD*DD];
__device__ __nv_bfloat16 g_wkvhi[2*DD*DD],        g_wkvlo[2*DD*DD];
__device__ __nv_bfloat16 g_pwhi [DD*(SS+2)*DD],   g_pwlo [DD*(SS+2)*DD];
__device__ __nv_bfloat16 g_hnhi [SS*BB*DD],       g_hnlo [SS*BB*DD];
__device__ __nv_bfloat16 g_chi  [BB*(SS+2)*DD],   g_clo  [BB*(SS+2)*DD];
__device__ __nv_bfloat16 g_Ahi  [DD*DD],          g_Alo  [DD*DD];
__device__ __nv_bfloat16 g_Athi [DD*DD],          g_Atlo [DD*DD];
__device__ __nv_bfloat16 g_A2hi [DD*DD],          g_A2lo [DD*DD];
__device__ __nv_bfloat16 g_w1hi [DD*DD],          g_w1lo [DD*DD];
__device__ __nv_bfloat16 g_Bmhi [DD*DD],          g_Bmlo [DD*DD];
__device__ __nv_bfloat16 g_aowhi[DD*DD],          g_aowlo[DD*DD];
__device__ __nv_bfloat16 g_pq0hi[2*BB*DD],        g_pq0lo[2*BB*DD];
__device__ __nv_bfloat16 g_pq1hi[2*BB*DD],        g_pq1lo[2*BB*DD];
__device__ __nv_bfloat16 g_ctxhi[BB*DD],          g_ctxlo[BB*DD];

// ---------------- helpers ----------------
__device__ __forceinline__ float warpAllReduceSum(float v) {
#pragma unroll
    for (int o = 16; o; o >>= 1) v += __shfl_xor_sync(0xffffffffu, v, o);
    return v;
}

__device__ __forceinline__ float blockAllReduceSum(float v, float* sbuf) {
    v = warpAllReduceSum(v);
    int w = threadIdx.x >> 5;
    if ((threadIdx.x & 31) == 0) sbuf[w] = v;
    __syncthreads();
    float r = 0.f;
#pragma unroll
    for (int i = 0; i < 8; i++) r += sbuf[i];
    __syncthreads();
    return r;
}

__device__ __forceinline__ float softplusf(float x) {
    return x > 0.f ? x + log1pf(expf(-x)) : log1pf(expf(x));
}
__device__ __forceinline__ float sigmf(float x) {
    return 1.f / (1.f + expf(-x));
}
__device__ __forceinline__ void split2(float v, __nv_bfloat16& h, __nv_bfloat16& l) {
    __nv_bfloat16 hb = __float2bfloat16(v);
    h = hb;
    l = __float2bfloat16(v - __bfloat162float(hb));
}

// ---------------- fp32 SIMT GEMM (kept for the q projection only) ----------------
__global__ __launch_bounds__(128) void gemm_nt_kernel(
    const float* __restrict__ A, int lda,
    const float* __restrict__ B, int ldb,
    float* __restrict__ C, int ldc,
    int K, const float* __restrict__ bias)
{
    __shared__ float As[32][33];
    __shared__ float Bs[32][33];

    int m0blk = blockIdx.y * 32;
    int n0blk = blockIdx.x * 32;
    int tid   = threadIdx.x;
    int kcol  = tid & 31;
    int rbase = tid >> 5;
    int tm = tid >> 4;
    int tn = tid & 15;
    int m0 = tm * 4, n0 = tn * 2;

    float acc[4][2] = {};
    const float* Ab = A + (long long)m0blk * lda;
    const float* Bb = B + (long long)n0blk * ldb;

    float pa[8], pb[8];
#pragma unroll
    for (int r = 0; r < 8; r++) {
        int row = rbase + r * 4;
        pa[r] = Ab[(long long)row * lda + kcol];
        pb[r] = Bb[(long long)row * ldb + kcol];
    }

    for (int kb = 0; kb < K; kb += 32) {
#pragma unroll
        for (int r = 0; r < 8; r++) {
            int row = rbase + r * 4;
            As[kcol][row] = pa[r];
            Bs[row][kcol] = pb[r];
        }
        __syncthreads();
        if (kb + 32 < K) {
#pragma unroll
            for (int r = 0; r < 8; r++) {
                int row = rbase + r * 4;
                pa[r] = Ab[(long long)row * lda + kb + 32 + kcol];
                pb[r] = Bb[(long long)row * ldb + kb + 32 + kcol];
            }
        }
#pragma unroll
        for (int k = 0; k < 32; k++) {
            float a0 = As[k][m0 + 0], a1 = As[k][m0 + 1];
            float a2 = As[k][m0 + 2], a3 = As[k][m0 + 3];
            float b0 = Bs[n0 + 0][k], b1 = Bs[n0 + 1][k];
            acc[0][0] += a0 * b0;  acc[0][1] += a0 * b1;
            acc[1][0] += a1 * b0;  acc[1][1] += a1 * b1;
            acc[2][0] += a2 * b0;  acc[2][1] += a2 * b1;
            acc[3][0] += a3 * b0;  acc[3][1] += a3 * b1;
        }
        __syncthreads();
    }

#pragma unroll
    for (int i = 0; i < 4; i++) {
        int gm = m0blk + m0 + i;
#pragma unroll
        for (int j = 0; j < 2; j++) {
            int gn = n0blk + n0 + j;
            float v = acc[i][j];
            if (bias) v += bias[gn];
            C[(long long)gm * ldc + gn] = v;
        }
    }
}

// ---------------- split-bf16 tensor-core GEMM (extended epilogue) ----------------
// V = rowscale(m) * ((Ahi+Alo)[z] @ (Bhi+Blo)[z]^T) + bias   (lo*lo dropped)
// then optionally: C (+=), atomic Yacc[(m&mask)], hi/lo split emit to Chi/Clo.
// Block 64x64, BK=32, 256 threads = 8 warps. M,N % 64 == 0, K % 32 == 0.
__device__ __forceinline__ void ldsm4(uint32_t* r, const __nv_bfloat16* p) {
    uint32_t a = (uint32_t)__cvta_generic_to_shared(p);
    asm volatile("ldmatrix.sync.aligned.m8n8.x4.shared.b16 {%0,%1,%2,%3}, [%4];"
        : "=r"(r[0]), "=r"(r[1]), "=r"(r[2]), "=r"(r[3]) : "r"(a));
}
#define MMA_BF16(d, a, b0_, b1_) \
    asm volatile("mma.sync.aligned.m16n8k16.row.col.f32.bf16.bf16.f32 " \
        "{%0,%1,%2,%3}, {%4,%5,%6,%7}, {%8,%9}, {%0,%1,%2,%3};" \
        : "+f"((d)[0]), "+f"((d)[1]), "+f"((d)[2]), "+f"((d)[3]) \
        : "r"((a)[0]), "r"((a)[1]), "r"((a)[2]), "r"((a)[3]), "r"(b0_), "r"(b1_))

__global__ __launch_bounds__(256) void gemm_bf16x2_nt_kernel(
    const __nv_bfloat16* __restrict__ Ahi, const __nv_bfloat16* __restrict__ Alo, long long aStr,
    const __nv_bfloat16* __restrict__ Bhi, const __nv_bfloat16* __restrict__ Blo, long long bStr,
    float* __restrict__ C, int ldc, long long cStr,
    int K,
    const float* __restrict__ bias, int biasStr,
    const float* __restrict__ rowscale,
    float* __restrict__ Yacc, int yaccMask,
    __nv_bfloat16* __restrict__ Chi, __nv_bfloat16* __restrict__ Clo,
    int accumulate)
{
    __shared__ __align__(16) __nv_bfloat16 sAhi[64*40];
    __shared__ __align__(16) __nv_bfloat16 sAlo[64*40];
    __shared__ __align__(16) __nv_bfloat16 sBhi[64*40];
    __shared__ __align__(16) __nv_bfloat16 sBlo[64*40];

    int z = blockIdx.z;
    Ahi += z * aStr;  Alo += z * aStr;
    Bhi += z * bStr;  Blo += z * bStr;
    if (C)   C   += z * cStr;
    if (Chi) { Chi += z * cStr; Clo += z * cStr; }

    int m0 = blockIdx.y * 64;
    int n0 = blockIdx.x * 64;
    int tid  = threadIdx.x;
    int lane = tid & 31;
    int wid  = tid >> 5;
    int wm = (wid & 3) << 4;
    int wn = (wid >> 2) << 5;

    int lrow = tid >> 2;
    int lk   = (tid & 3) << 3;

    const __nv_bfloat16* gAhi = Ahi + (long long)(m0 + lrow) * K + lk;
    const __nv_bfloat16* gAlo = Alo + (long long)(m0 + lrow) * K + lk;
    const __nv_bfloat16* gBhi = Bhi + (long long)(n0 + lrow) * K + lk;
    const __nv_bfloat16* gBlo = Blo + (long long)(n0 + lrow) * K + lk;
    int srow = lrow * 40 + lk;

    int a_off = (wm + (lane & 15)) * 40 + ((lane >> 4) << 3);
    int b_off = (wn + (lane & 7) + ((lane >> 4) << 3)) * 40 + (((lane >> 3) & 1) << 3);

    float d[4][4];
#pragma unroll
    for (int i = 0; i < 4; i++)
#pragma unroll
        for (int j = 0; j < 4; j++) d[i][j] = 0.f;

    uint4 pA0 = *(const uint4*)gAhi;
    uint4 pA1 = *(const uint4*)gAlo;
    uint4 pB0 = *(const uint4*)gBhi;
    uint4 pB1 = *(const uint4*)gBlo;

    for (int kb = 0; kb < K; kb += 32) {
        *(uint4*)(sAhi + srow) = pA0;
        *(uint4*)(sAlo + srow) = pA1;
        *(uint4*)(sBhi + srow) = pB0;
        *(uint4*)(sBlo + srow) = pB1;
        __syncthreads();
        if (kb + 32 < K) {
            pA0 = *(const uint4*)(gAhi + kb + 32);
            pA1 = *(const uint4*)(gAlo + kb + 32);
            pB0 = *(const uint4*)(gBhi + kb + 32);
            pB1 = *(const uint4*)(gBlo + kb + 32);
        }
#pragma unroll
        for (int kk = 0; kk < 32; kk += 16) {
            uint32_t ah[4], al[4], bh0[4], bl0[4], bh1[4], bl1[4];
            ldsm4(ah,  sAhi + a_off + kk);
            ldsm4(al,  sAlo + a_off + kk);
            ldsm4(bh0, sBhi + b_off + kk);
            ldsm4(bl0, sBlo + b_off + kk);
            ldsm4(bh1, sBhi + b_off + 16*40 + kk);
            ldsm4(bl1, sBlo + b_off + 16*40 + kk);
            MMA_BF16(d[0], ah, bh0[0], bh0[1]);
            MMA_BF16(d[1], ah, bh0[2], bh0[3]);
            MMA_BF16(d[2], ah, bh1[0], bh1[1]);
            MMA_BF16(d[3], ah, bh1[2], bh1[3]);
            MMA_BF16(d[0], ah, bl0[0], bl0[1]);
            MMA_BF16(d[1], ah, bl0[2], bl0[3]);
            MMA_BF16(d[2], ah, bl1[0], bl1[1]);
            MMA_BF16(d[3], ah, bl1[2], bl1[3]);
            MMA_BF16(d[0], al, bh0[0], bh0[1]);
            MMA_BF16(d[1], al, bh0[2], bh0[3]);
            MMA_BF16(d[2], al, bh1[0], bh1[1]);
            MMA_BF16(d[3], al, bh1[2], bh1[3]);
        }
        __syncthreads();
    }

    int gid = lane >> 2, tig = lane & 3;
#pragma unroll
    for (int rr = 0; rr < 2; rr++) {
        int gm = m0 + wm + gid + rr * 8;
        float s = rowscale ? rowscale[gm] : 1.f;
#pragma unroll
        for (int nf = 0; nf < 4; nf++) {
#pragma unroll
            for (int jj = 0; jj < 2; jj++) {
                int gn = n0 + wn + nf * 8 + tig * 2 + jj;
                float v = d[nf][rr * 2 + jj] * s;
                if (bias) v += bias[z * biasStr + gn];
                long long ci = (long long)gm * ldc + gn;
                if (C) {
                    if (accumulate) v += C[ci];
                    C[ci] = v;
                }
                if (Yacc) atomicAdd(&Yacc[(long long)(gm & yaccMask) * ldc + gn], v);
                if (Chi) {
                    __nv_bfloat16 h, l;
                    split2(v, h, l);
                    Chi[ci] = h;
                    Clo[ci] = l;
                }
            }
        }
    }
}

// ---------------- batched fp32 -> bf16 hi/lo split ----------------
struct SplitSeg { const float* src; __nv_bfloat16* hi; __nv_bfloat16* lo; int n; };
struct SplitArgs { SplitSeg seg[11]; };

__global__ void split_kernel(SplitArgs a) {
    SplitSeg s = a.seg[blockIdx.y];
    for (int i = blockIdx.x * blockDim.x + threadIdx.x; i < s.n;
         i += gridDim.x * blockDim.x) {
        float v = s.src[i];
        __nv_bfloat16 h, l;
        split2(v, h, l);
        s.hi[i] = h;
        s.lo[i] = l;
    }
}

// ---------------- 512x512 transpose -> bf16 hi/lo ----------------
__global__ __launch_bounds__(256) void transpose_split_kernel(
    const float* __restrict__ A,
    __nv_bfloat16* __restrict__ Athi, __nv_bfloat16* __restrict__ Atlo)
{
    __shared__ float tile[32][33];
    int bx = blockIdx.x & 15, by = blockIdx.x >> 4;
    int tx = threadIdx.x & 31, ty = threadIdx.x >> 5;
#pragma unroll
    for (int r = 0; r < 4; r++)
        tile[ty + r * 8][tx] = A[(by * 32 + ty + r * 8) * DD + bx * 32 + tx];
    __syncthreads();
#pragma unroll
    for (int r = 0; r < 4; r++) {
        float v = tile[tx][ty + r * 8];
        __nv_bfloat16 h, l;
        split2(v, h, l);
        int idx = (bx * 32 + ty + r * 8) * DD + by * 32 + tx;
        Athi[idx] = h;
        Atlo[idx] = l;
    }
}

// ---------------- LN -> gelu -> delta ----------------
__global__ __launch_bounds__(256) void ln_gelu_delta_kernel(
    const float* __restrict__ H,
    const float* __restrict__ g, const float* __restrict__ beta,
    const float* __restrict__ w2, const float* __restrict__ b2,
    float* __restrict__ delta)
{
    __shared__ float sbuf[8];
    int row = blockIdx.x;
    int t = threadIdx.x;
    const float* hr = H + row * DD;
    float x0 = hr[t], x1 = hr[t + 256];

    float s  = blockAllReduceSum(x0 + x1, sbuf);
    float ss = blockAllReduceSum(x0 * x0 + x1 * x1, sbuf);
    float mean = s * (1.f / DD);
    float var  = ss * (1.f / DD) - mean * mean;
    float inv  = rsqrtf(var + 1e-5f);

    float y0 = (x0 - mean) * inv * g[t]       + beta[t];
    float y1 = (x1 - mean) * inv * g[t + 256] + beta[t + 256];
    y0 = 0.5f * y0 * (1.f + erff(y0 * 0.70710678118654752f));
    y1 = 0.5f * y1 * (1.f + erff(y1 * 0.70710678118654752f));

    float d = blockAllReduceSum(y0 * w2[t] + y1 * w2[t + 256], sbuf);
    if (t == 0) delta[row] = softplusf(d + b2[0]);
}

// ---------------- final layernorm ----------------
__global__ __launch_bounds__(256) void ln_out_kernel(
    const float* __restrict__ H,
    const float* __restrict__ g, const float* __restrict__ beta,
    float* __restrict__ out)
{
    __shared__ float sbuf[8];
    int row = blockIdx.x;
    int t = threadIdx.x;
    const float* hr = H + row * DD;
    float x0 = hr[t], x1 = hr[t + 256];
    float s  = blockAllReduceSum(x0 + x1, sbuf);
    float ss = blockAllReduceSum(x0 * x0 + x1 * x1, sbuf);
    float mean = s * (1.f / DD);
    float var  = ss * (1.f / DD) - mean * mean;
    float inv  = rsqrtf(var + 1e-5f);
    out[row * DD + t]       = (x0 - mean) * inv * g[t]       + beta[t];
    out[row * DD + t + 256] = (x1 - mean) * inv * g[t + 256] + beta[t + 256];
}

// ---------------- SSM prep: hssm = h_prev + dbx; rs tables ----------------
__global__ void ssm_prep_kernel(
    const float* __restrict__ h_prev, const float* __restrict__ dbx,
    const float* __restrict__ delta,
    float* __restrict__ hssm, float* __restrict__ rs)
{
    int idx = blockIdx.x * blockDim.x + threadIdx.x;
    if (idx < BB * DD) {
        hssm[idx] = h_prev[idx] + dbx[idx];
    }
    if (idx < CHAIN_M * 2 * BB) {
        int m  = idx / (2 * BB) + 1;
        int c  = idx % (2 * BB);
        int b  = c & (BB - 1);
        float d = delta[b];
        float coef = (c < BB) ? 1.f / (float)((2 * m - 1) * (2 * m))
                              : 1.f / (float)((2 * m) * (2 * m + 1));
        rs[idx] = d * d * coef;
    }
}

// ---------------- LSTM elementwise (emits h hi/lo bf16) ----------------
__global__ void lstm_elem_kernel(
    const float* __restrict__ gates, const float* __restrict__ c_in,
    const float* __restrict__ decays,
    float* __restrict__ h_out, float* __restrict__ c_out,
    __nv_bfloat16* __restrict__ hhi, __nv_bfloat16* __restrict__ hlo)
{
    int idx = blockIdx.x * blockDim.x + threadIdx.x;
    if (idx >= SS * BB * DD) return;
    int d  = idx & (DD - 1);
    int bs = idx >> 9;
    int s  = bs >> 8;
    const float* grow = gates + (long long)bs * (4 * DD);
    float i = sigmf(grow[d]);
    float f = sigmf(grow[DD + d]);
    float gg = tanhf(grow[2 * DD + d]);
    float o = sigmf(grow[3 * DD + d]);
    float c = c_in[idx];
    float craw = f * c + i * gg;
    float dec = decays[s];
    float hv = o * tanhf(craw);
    h_out[idx] = hv;
    c_out[idx] = dec * c + (1.f - dec) * craw;
    __nv_bfloat16 hb, lb;
    split2(hv, hb, lb);
    hhi[idx] = hb;
    hlo[idx] = lb;
}

// ---------------- tiny attention; emits ctx hi/lo bf16 ----------------
__global__ __launch_bounds__(256) void attn_kernel(
    const float* __restrict__ q, const float* __restrict__ kv,
    __nv_bfloat16* __restrict__ chi, __nv_bfloat16* __restrict__ clo)
{
    int b = blockIdx.x;
    int h = threadIdx.x >> 5;
    int l = threadIdx.x & 31;
    int e0 = h * HD_ + l;
    int e1 = e0 + 32;
    float q0 = q[b * DD + e0], q1 = q[b * DD + e1];

    float sc[SS];
#pragma unroll
    for (int s = 0; s < SS; s++) {
        const float* ks = kv + ((long long)s * BB + b) * (2 * DD);
        float p = q0 * ks[e0] + q1 * ks[e1];
        p = warpAllReduceSum(p);
        sc[s] = p * 0.125f;
    }
    float m = fmaxf(sc[0], fmaxf(sc[1], sc[2]));
    float e[SS], sum = 0.f;
#pragma unroll
    for (int s = 0; s < SS; s++) { e[s] = expf(sc[s] - m); sum += e[s]; }
    float rinv = 1.f / sum;
    float c0 = 0.f, c1 = 0.f;
#pragma unroll
    for (int s = 0; s < SS; s++) {
        const float* vs = kv + ((long long)s * BB + b) * (2 * DD) + DD;
        float a = e[s] * rinv;
        c0 += a * vs[e0];
        c1 += a * vs[e1];
    }
    __nv_bfloat16 hh, ll;
    split2(c0, hh, ll);
    chi[b * DD + e0] = hh;  clo[b * DD + e0] = ll;
    split2(c1, hh, ll);
    chi[b * DD + e1] = hh;  clo[b * DD + e1] = ll;
}

// ---------------- pack combined -> bf16 hi/lo; also emit hssm out ----------------
__global__ void pack_comb_kernel(
    const float* __restrict__ hssm, const float* __restrict__ fused,
    const float* __restrict__ h_new,
    __nv_bfloat16* __restrict__ chi, __nv_bfloat16* __restrict__ clo,
    float* __restrict__ out_hssm)
{
    int idx = blockIdx.x * blockDim.x + threadIdx.x;
    const int TOT = BB * (SS + 2) * DD;
    if (idx >= TOT) return;
    int d = idx & (DD - 1);
    int rest = idx >> 9;
    int j = rest % (SS + 2);
    int b = rest / (SS + 2);
    float v;
    if (j == 0) {
        v = hssm[b * DD + d];
        out_hssm[b * DD + d] = v;
    } else if (j == 1) {
        v = fused[b * DD + d];
    } else {
        v = h_new[((long long)(j - 2) * BB + b) * DD + d];
    }
    __nv_bfloat16 h, l;
    split2(v, h, l);
    chi[idx] = h;
    clo[idx] = l;
}

// ---------------- host launch (single stream) ----------------
extern "C" void kernel_launch(void* const* d_in, const int* in_sizes, int n_in,
                              void* d_out, int out_size)
{
    const float* x        = (const float*)d_in[0];
    const float* h_prev   = (const float*)d_in[1];
    const float* lstm_h   = (const float*)d_in[2];
    const float* lstm_c   = (const float*)d_in[3];
    const float* Amat     = (const float*)d_in[4];
    const float* Bm       = (const float*)d_in[5];
    const float* dn_w1    = (const float*)d_in[6];
    const float* dn_b1    = (const float*)d_in[7];
    const float* dn_g     = (const float*)d_in[8];
    const float* dn_beta  = (const float*)d_in[9];
    const float* dn_w2    = (const float*)d_in[10];
    const float* dn_b2    = (const float*)d_in[11];
    const float* lstm_wih = (const float*)d_in[12];
    const float* lstm_whh = (const float*)d_in[13];
    const float* lstm_bih = (const float*)d_in[14];
    const float* lstm_bhh = (const float*)d_in[15];
    const float* decays   = (const float*)d_in[16];
    const float* attn_in_w= (const float*)d_in[17];
    const float* attn_in_b= (const float*)d_in[18];
    const float* attn_out_w=(const float*)d_in[19];
    const float* attn_out_b=(const float*)d_in[20];
    const float* proj_w   = (const float*)d_in[21];
    const float* proj_b   = (const float*)d_in[22];
    const float* proj_g   = (const float*)d_in[23];
    const float* proj_beta= (const float*)d_in[24];

    float* out = (float*)d_out;
    const long long OFF_HSSM = (long long)BB * DD;
    const long long OFF_H    = 2 * OFF_HSSM;
    const long long OFF_C    = OFF_H + (long long)SS * BB * DD;

    float *h1pre, *delta, *dbx, *rs, *hssm, *gates, *qb, *kv, *fused, *outpre;
    cudaGetSymbolAddress((void**)&h1pre,  g_h1pre);
    cudaGetSymbolAddress((void**)&delta,  g_delta);
    cudaGetSymbolAddress((void**)&dbx,    g_dbx);
    cudaGetSymbolAddress((void**)&rs,     g_rs);
    cudaGetSymbolAddress((void**)&hssm,   g_hssm);
    cudaGetSymbolAddress((void**)&gates,  g_gates);
    cudaGetSymbolAddress((void**)&qb,     g_q);
    cudaGetSymbolAddress((void**)&kv,     g_kv);
    cudaGetSymbolAddress((void**)&fused,  g_fused);
    cudaGetSymbolAddress((void**)&outpre, g_outpre);

    __nv_bfloat16 *xhi,*xlo,*lhhi,*lhlo,*wihhi,*wihlo,*whhhi,*whhlo,
                  *wkvhi,*wkvlo,*pwhi,*pwlo,*hnhi,*hnlo,*chi,*clo,
                  *Ahi,*Alo,*Athi,*Atlo,*A2hi,*A2lo,*w1hi,*w1lo,
                  *Bmhi,*Bmlo,*aowhi,*aowlo,*pq0hi,*pq0lo,*pq1hi,*pq1lo,
                  *ctxhi,*ctxlo;
    cudaGetSymbolAddress((void**)&xhi,   g_xhi);   cudaGetSymbolAddress((void**)&xlo,   g_xlo);
    cudaGetSymbolAddress((void**)&lhhi,  g_lhhi);  cudaGetSymbolAddress((void**)&lhlo,  g_lhlo);
    cudaGetSymbolAddress((void**)&wihhi, g_wihhi); cudaGetSymbolAddress((void**)&wihlo, g_wihlo);
    cudaGetSymbolAddress((void**)&whhhi, g_whhhi); cudaGetSymbolAddress((void**)&whhlo, g_whhlo);
    cudaGetSymbolAddress((void**)&wkvhi, g_wkvhi); cudaGetSymbolAddress((void**)&wkvlo, g_wkvlo);
    cudaGetSymbolAddress((void**)&pwhi,  g_pwhi);  cudaGetSymbolAddress((void**)&pwlo,  g_pwlo);
    cudaGetSymbolAddress((void**)&hnhi,  g_hnhi);  cudaGetSymbolAddress((void**)&hnlo,  g_hnlo);
    cudaGetSymbolAddress((void**)&chi,   g_chi);   cudaGetSymbolAddress((void**)&clo,   g_clo);
    cudaGetSymbolAddress((void**)&Ahi,   g_Ahi);   cudaGetSymbolAddress((void**)&Alo,   g_Alo);
    cudaGetSymbolAddress((void**)&Athi,  g_Athi);  cudaGetSymbolAddress((void**)&Atlo,  g_Atlo);
    cudaGetSymbolAddress((void**)&A2hi,  g_A2hi);  cudaGetSymbolAddress((void**)&A2lo,  g_A2lo);
    cudaGetSymbolAddress((void**)&w1hi,  g_w1hi);  cudaGetSymbolAddress((void**)&w1lo,  g_w1lo);
    cudaGetSymbolAddress((void**)&Bmhi,  g_Bmhi);  cudaGetSymbolAddress((void**)&Bmlo,  g_Bmlo);
    cudaGetSymbolAddress((void**)&aowhi, g_aowhi); cudaGetSymbolAddress((void**)&aowlo, g_aowlo);
    cudaGetSymbolAddress((void**)&pq0hi, g_pq0hi); cudaGetSymbolAddress((void**)&pq0lo, g_pq0lo);
    cudaGetSymbolAddress((void**)&pq1hi, g_pq1hi); cudaGetSymbolAddress((void**)&pq1lo, g_pq1lo);
    cudaGetSymbolAddress((void**)&ctxhi, g_ctxhi); cudaGetSymbolAddress((void**)&ctxlo, g_ctxlo);

    // full-feature bf16 gemm wrapper
    auto gemmb = [&](const __nv_bfloat16* Ah, const __nv_bfloat16* Al, long long aStr,
                     const __nv_bfloat16* Bh, const __nv_bfloat16* Bl, long long bStr,
                     float* C, int ldc, long long cStr,
                     int M, int N, int K, int Z,
                     const float* bias, int biasStr,
                     const float* rsc, float* Yacc, int yaccMask,
                     __nv_bfloat16* Chi, __nv_bfloat16* Clo, int acc) {
        dim3 grid(N / 64, M / 64, Z);
        gemm_bf16x2_nt_kernel<<<grid, 256>>>(Ah, Al, aStr, Bh, Bl, bStr,
                                             C, ldc, cStr, K, bias, biasStr,
                                             rsc, Yacc, yaccMask, Chi, Clo, acc);
    };
    const int FULLMASK = 0x7fffffff;

    // 0) batched splits of everything derived purely from inputs.
    //    h_prev split lands directly in pq0[0:BB*DD) = even-term seed.
    {
        SplitArgs sa;
        sa.seg[0]  = { x,         xhi,   xlo,   BB * DD };
        sa.seg[1]  = { lstm_h,    lhhi,  lhlo,  SS * BB * DD };
        sa.seg[2]  = { lstm_wih,  wihhi, wihlo, SS * 4 * DD * DD };
        sa.seg[3]  = { lstm_whh,  whhhi, whhlo, SS * 4 * DD * DD };
        sa.seg[4]  = { attn_in_w + (long long)DD * DD, wkvhi, wkvlo, 2 * DD * DD };
        sa.seg[5]  = { proj_w,    pwhi,  pwlo,  DD * (SS + 2) * DD };
        sa.seg[6]  = { dn_w1,     w1hi,  w1lo,  DD * DD };
        sa.seg[7]  = { Bm,        Bmhi,  Bmlo,  DD * DD };
        sa.seg[8]  = { Amat,      Ahi,   Alo,   DD * DD };
        sa.seg[9]  = { attn_out_w,aowhi, aowlo, DD * DD };
        sa.seg[10] = { h_prev,    pq0hi, pq0lo, BB * DD };
        split_kernel<<<dim3(512, 11), 256>>>(sa);
    }

    // 1) At (bf16) ; A2 = A @ A via B-op = At, emit hi/lo only
    transpose_split_kernel<<<256, 256>>>(Amat, Athi, Atlo);
    gemmb(Ahi, Alo, 0, Athi, Atlo, 0, nullptr, DD, 0, DD, DD, DD, 1,
          nullptr, 0, nullptr, nullptr, 0, A2hi, A2lo, 0);

    // 2) delta-net head: h1pre = x @ dn_w1^T + b1 (bf16)
    gemmb(xhi, xlo, 0, w1hi, w1lo, 0, h1pre, DD, 0, BB, DD, DD, 1,
          dn_b1, 0, nullptr, nullptr, 0, nullptr, nullptr, 0);
    ln_gelu_delta_kernel<<<BB, 256>>>(h1pre, dn_g, dn_beta, dn_w2, dn_b2, delta);

    // 3) dbx = delta * (x @ Bm^T) (bf16, rowscale)
    gemmb(xhi, xlo, 0, Bmhi, Bmlo, 0, dbx, DD, 0, BB, DD, DD, 1,
          nullptr, 0, delta, nullptr, 0, nullptr, nullptr, 0);

    // 4) prep: hssm = h_prev + dbx ; rs tables
    ssm_prep_kernel<<<(BB * DD + 255) / 256, 256>>>(h_prev, dbx, delta, hssm, rs);

    // 5) q0 = delta * (h_prev @ A^T): A-op = pq0[0:256) (h_prev bf16), B-op = A.
    //    hssm += q0 (term k=1); emit hi/lo into pq0 rows [256:512).
    gemmb(pq0hi, pq0lo, 0, Ahi, Alo, 0, nullptr, DD, 0, BB, DD, DD, 1,
          nullptr, 0, delta, hssm, FULLMASK,
          pq0hi + (long long)BB * DD, pq0lo + (long long)BB * DD, 0);

    // 6) chain m=1..CHAIN_M (bf16 tensor cores):
    //    [p;q]_m = rs_m(row) * ([p;q]_{m-1} @ A2^T); hssm += both halves (atomic)
    {
        __nv_bfloat16 *tinh = pq0hi, *tinl = pq0lo, *touth = pq1hi, *toutl = pq1lo;
        for (int m = 1; m <= CHAIN_M; m++) {
            gemmb(tinh, tinl, 0, A2hi, A2lo, 0, nullptr, DD, 0, 2 * BB, DD, DD, 1,
                  nullptr, 0, rs + (long long)(m - 1) * 2 * BB,
                  hssm, BB - 1, touth, toutl, 0);
            __nv_bfloat16* t;
            t = tinh; tinh = touth; touth = t;
            t = tinl; tinl = toutl; toutl = t;
        }
    }

    // 7) LSTM gates (bf16)
    gemmb(xhi, xlo, 0, wihhi, wihlo, (long long)4 * DD * DD,
          gates, 4 * DD, (long long)BB * 4 * DD, BB, 4 * DD, DD, SS,
          lstm_bih, 4 * DD, nullptr, nullptr, 0, nullptr, nullptr, 0);
    gemmb(lhhi, lhlo, (long long)BB * DD, whhhi, whhlo, (long long)4 * DD * DD,
          gates, 4 * DD, (long long)BB * 4 * DD, BB, 4 * DD, DD, SS,
          lstm_bhh, 4 * DD, nullptr, nullptr, 0, nullptr, nullptr, 1);
    lstm_elem_kernel<<<(SS * BB * DD + 255) / 256, 256>>>(
        gates, lstm_c, decays, out + OFF_H, out + OFF_C, hnhi, hnlo);

    // 8) fused k|v projection (bf16)
    gemmb(hnhi, hnlo, (long long)BB * DD, wkvhi, wkvlo, 0,
          kv, 2 * DD, (long long)BB * 2 * DD, BB, 2 * DD, DD, SS,
          attn_in_b + DD, 0, nullptr, nullptr, 0, nullptr, nullptr, 0);

    // 9) q = hssm @ Wq^T + bq (fp32 — hssm finalized by chain atomics)
    {
        dim3 grid(DD / 32, BB / 32, 1);
        gemm_nt_kernel<<<grid, 128>>>(hssm, DD, attn_in_w, DD, qb, DD, DD, attn_in_b);
    }

    // 10) attention (emits ctx hi/lo) + out proj (bf16)
    attn_kernel<<<BB, 256>>>(qb, kv, ctxhi, ctxlo);
    gemmb(ctxhi, ctxlo, 0, aowhi, aowlo, 0, fused, DD, 0, BB, DD, DD, 1,
          attn_out_b, 0, nullptr, nullptr, 0, nullptr, nullptr, 0);

    // 11) pack (bf16 hi/lo + hssm out) + big proj (bf16) + final LN
    pack_comb_kernel<<<(BB * (SS + 2) * DD + 255) / 256, 256>>>(
        hssm, fused, out + OFF_H, chi, clo, out + OFF_HSSM);
    gemmb(chi, clo, 0, pwhi, pwlo, 0,
          outpre, DD, 0, BB, DD, (SS + 2) * DD, 1,
          proj_b, 0, nullptr, nullptr, 0, nullptr, nullptr, 0);
    ln_out_kernel<<<BB, 256>>>(outpre, proj_g, proj_beta, out);
}